// round 15
// baseline (speedup 1.0000x reference)
#include <cuda_runtime.h>
#include <cuda_bf16.h>
#include <cuda_fp16.h>
#include <cstdint>

// Problem constants (match reference setup_inputs)
#define NNODES 50000
#define NEDGES 640000
// IN_DIM = 128, HID = 128, OUT = 64

// ---------------------------------------------------------------------------
// Device scratch (allocation-free rule: __device__ globals)
// ---------------------------------------------------------------------------
__device__ float  g_C1s[NNODES * 128];    // layer1 self projection (fp32)
__device__ __half g_P1[NNODES * 128];     // layer1 neighbor projection (fp16)
__device__ float4 g_SUM1[NNODES * 32];    // layer1 gather sums (fp32)
__device__ __half g_H1[NNODES * 128];     // hidden activations (fp16)
__device__ float  g_C2s[NNODES * 64];     // layer2 self projection (fp32)
__device__ __half g_P2[NNODES * 64];      // layer2 neighbor projection (fp16)
// fp16 hi/lo split weights, SCALED BY 256, plain [n][k] row-major
__device__ __align__(16) __half g_W1H[256 * 128];
__device__ __align__(16) __half g_W1L[256 * 128];
__device__ __align__(16) __half g_W2H[128 * 128];
__device__ __align__(16) __half g_W2L[128 * 128];
// CSR build scratch
__device__ int    g_cnt[NNODES];
__device__ int    g_off[NNODES];
__device__ int    g_cur[NNODES];
__device__ int    g_csr[NEDGES];
__device__ int    g_blkSums[128];

// ---------------------------------------------------------------------------
// Helpers
// ---------------------------------------------------------------------------
__device__ __forceinline__ uint32_t smem_u32(const void* p) {
    uint32_t a;
    asm("{ .reg .u64 t; cvta.to.shared.u64 t, %1; cvt.u32.u64 %0, t; }"
        : "=r"(a) : "l"(p));
    return a;
}
__device__ __forceinline__ void ldsm4(uint32_t* r, uint32_t addr) {
    asm volatile("ldmatrix.sync.aligned.m8n8.x4.shared.b16 {%0,%1,%2,%3}, [%4];"
                 : "=r"(r[0]), "=r"(r[1]), "=r"(r[2]), "=r"(r[3]) : "r"(addr));
}
__device__ __forceinline__ void mma_f16(float* d, const uint32_t* a,
                                        uint32_t b0, uint32_t b1) {
    asm volatile(
        "mma.sync.aligned.m16n8k16.row.col.f32.f16.f16.f32 "
        "{%0,%1,%2,%3}, {%4,%5,%6,%7}, {%8,%9}, {%0,%1,%2,%3};"
        : "+f"(d[0]), "+f"(d[1]), "+f"(d[2]), "+f"(d[3])
        : "r"(a[0]), "r"(a[1]), "r"(a[2]), "r"(a[3]), "r"(b0), "r"(b1));
}
__device__ __forceinline__ float4 f4add(float4 a, float4 b) {
    return make_float4(a.x + b.x, a.y + b.y, a.z + b.z, a.w + b.w);
}
// Accumulate 4 fp16 values (as uint2) into a float4
__device__ __forceinline__ float4 f4addh(float4 a, uint2 v) {
    __half2 p0 = *reinterpret_cast<__half2*>(&v.x);
    __half2 p1 = *reinterpret_cast<__half2*>(&v.y);
    float2 f0 = __half22float2(p0);
    float2 f1 = __half22float2(p1);
    return make_float4(a.x + f0.x, a.y + f0.y, a.z + f1.x, a.w + f1.y);
}

// ---------------------------------------------------------------------------
// CSR build: zero counts -> histogram -> scanA -> scanC(+parallel prefix) -> scatter
// ---------------------------------------------------------------------------
__global__ void zero_cnt_kernel() {
    int i = blockIdx.x * blockDim.x + threadIdx.x;
    if (i < NNODES) g_cnt[i] = 0;
}
__global__ void hist_kernel(const int* __restrict__ dst) {
    int e = blockIdx.x * blockDim.x + threadIdx.x;
    if (e < NEDGES) atomicAdd(&g_cnt[dst[e]], 1);
}
__global__ void scanA_kernel() {
    __shared__ int s[512];
    int b = blockIdx.x, t = threadIdx.x;
    int i = b * 512 + t;
    int v = (i < NNODES) ? g_cnt[i] : 0;
    s[t] = v;
    __syncthreads();
#pragma unroll
    for (int d = 1; d < 512; d <<= 1) {
        int x = (t >= d) ? s[t - d] : 0;
        __syncthreads();
        s[t] += x;
        __syncthreads();
    }
    if (i < NNODES) g_off[i] = s[t] - v;
    if (t == 511) g_blkSums[b] = s[t];
}
__global__ void scanC_kernel(int nblocks) {
    __shared__ int s[128];
    int t = threadIdx.x;
    if (t < 128) s[t] = (t < nblocks) ? g_blkSums[t] : 0;
    __syncthreads();
#pragma unroll
    for (int d = 1; d < 128; d <<= 1) {
        int x = 0;
        if (t < 128 && t >= d) x = s[t - d];
        __syncthreads();
        if (t < 128) s[t] += x;
        __syncthreads();
    }
    int i = blockIdx.x * blockDim.x + t;
    if (i < NNODES) {
        int blk = i >> 9;
        int pre = (blk == 0) ? 0 : s[blk - 1];
        int o = g_off[i] + pre;
        g_off[i] = o;
        g_cur[i] = o;
    }
}
__global__ void scatter_kernel(const int* __restrict__ src,
                               const int* __restrict__ dst) {
    int e = blockIdx.x * blockDim.x + threadIdx.x;
    if (e < NEDGES) {
        int d = dst[e];
        int p = atomicAdd(&g_cur[d], 1);
        g_csr[p] = src[e];
    }
}

// ---------------------------------------------------------------------------
// Weight prep: split fp32 -> fp16 hi/lo SCALED BY 256, plain [n][k] layout.
// ---------------------------------------------------------------------------
__global__ void prep_w_kernel(const float* __restrict__ Ws1,
                              const float* __restrict__ Wn1,
                              const float* __restrict__ Ws2,
                              const float* __restrict__ Wn2) {
    int i = blockIdx.x * blockDim.x + threadIdx.x;
    if (i < 256 * 128) {
        int n = i >> 7, k = i & 127;
        float w = (n < 128) ? Ws1[n * 128 + k] : Wn1[(n - 128) * 128 + k];
        float ws = w * 256.0f;
        __half h = __float2half_rn(ws);
        g_W1H[i] = h;
        g_W1L[i] = __float2half_rn(ws - __half2float(h));
    }
    if (i < 128 * 128) {
        int n = i >> 7, k = i & 127;
        float w = (n < 64) ? Ws2[n * 128 + k] : Wn2[(n - 64) * 128 + k];
        float ws = w * 256.0f;
        __half h = __float2half_rn(ws);
        g_W2H[i] = h;
        g_W2L[i] = __float2half_rn(ws - __half2float(h));
    }
}

// ---------------------------------------------------------------------------
// Tensor-core GEMM (round-13 exact template). NSELF=NOUT -> all fp32 Cself;
// NSELF=0 -> all fp16 Pneigh; mixed supported too.
// ---------------------------------------------------------------------------
template <int NOUT, int NSELF, bool AFP32>
__global__ void __launch_bounds__(256, 3)
gemm_mma_kernel(const void* __restrict__ Asrc,
                const __half* __restrict__ WHg,
                const __half* __restrict__ WLg,
                float* __restrict__ Cself,
                __half* __restrict__ Pneigh, int M) {
    constexpr int ASTR = 136;
    constexpr int WSTR = 136;
    constexpr int NP = (NOUT - NSELF) > 0 ? (NOUT - NSELF) : 1;
    extern __shared__ __half smem[];
    __half* sA  = smem;                    // 128*136 fp16
    __half* sWH = sA + 128 * ASTR;         // 64*136
    __half* sWL = sWH + 64 * WSTR;

    int tid = threadIdx.x;
    int warp = tid >> 5, lane = tid & 31;
    int rg = warp >> 1;                    // row group of 32 (0..3)
    int cg = warp & 1;                     // col group of 32 (0..1)
    int base = blockIdx.x * 128;

    // ---- Load A tile (128 rows x 128), single fp16 plane in SMEM ----
    {
        int row = tid >> 1;
        int cbase = (tid & 1) * 64;
        int grow = base + row;
        if (AFP32) {
            const float4* A4 = reinterpret_cast<const float4*>(Asrc);
#pragma unroll
            for (int i = 0; i < 8; i++) {
                float4 u, v;
                if (grow < M) {
                    u = A4[(size_t)grow * 32 + (cbase >> 2) + 2 * i];
                    v = A4[(size_t)grow * 32 + (cbase >> 2) + 2 * i + 1];
                } else {
                    u = v = make_float4(0.f, 0.f, 0.f, 0.f);
                }
                alignas(16) __half2 hp[4];
                hp[0] = __floats2half2_rn(u.x, u.y);
                hp[1] = __floats2half2_rn(u.z, u.w);
                hp[2] = __floats2half2_rn(v.x, v.y);
                hp[3] = __floats2half2_rn(v.z, v.w);
                int off = row * ASTR + cbase + 8 * i;
                *reinterpret_cast<uint4*>(sA + off) = *reinterpret_cast<uint4*>(hp);
            }
        } else {
            const uint4* A4 = reinterpret_cast<const uint4*>(Asrc);  // 8 halves each
#pragma unroll
            for (int i = 0; i < 8; i++) {
                uint4 u;
                if (grow < M) u = A4[(size_t)grow * 16 + (cbase >> 3) + i];
                else          u = make_uint4(0, 0, 0, 0);
                int off = row * ASTR + cbase + 8 * i;
                *reinterpret_cast<uint4*>(sA + off) = u;
            }
        }
    }

    // Per-thread ldmatrix base offsets
    int g8 = lane >> 3, j8 = lane & 7;
    uint32_t aA0 = smem_u32(sA) +
                   (uint32_t)(((rg * 32 + (g8 & 1) * 8 + j8) * ASTR + (g8 >> 1) * 8) * 2);
    constexpr uint32_t A_MB = 16u * ASTR * 2u;        // m-block stride
    uint32_t aB0 = smem_u32(sWH) +
                   (uint32_t)(((cg * 32 + (g8 >> 1) * 8 + j8) * WSTR + (g8 & 1) * 8) * 2);
    constexpr uint32_t B_NP = 16u * WSTR * 2u;        // nblk-pair stride
    constexpr uint32_t B_LO = 64u * WSTR * 2u;        // hi->lo plane

#pragma unroll
    for (int h = 0; h < NOUT / 64; h++) {
        __syncthreads();
        // ---- Load W strip (64 cols x 128 k) hi/lo fp16 ----
        {
            int n = tid >> 2;
            int q4 = (tid & 3) * 4;
            const uint4* gh = reinterpret_cast<const uint4*>(WHg) +
                              (size_t)(h * 64 + n) * 16 + q4;
            const uint4* gl = reinterpret_cast<const uint4*>(WLg) +
                              (size_t)(h * 64 + n) * 16 + q4;
            uint4* sh = reinterpret_cast<uint4*>(sWH + n * WSTR) + q4;
            uint4* sl = reinterpret_cast<uint4*>(sWL + n * WSTR) + q4;
#pragma unroll
            for (int i = 0; i < 4; i++) {
                sh[i] = gh[i];
                sl[i] = gl[i];
            }
        }
        __syncthreads();

        float acc[32];
#pragma unroll
        for (int i = 0; i < 32; i++) acc[i] = 0.f;

#pragma unroll
        for (int ks = 0; ks < 8; ks++) {
            uint32_t kb = (uint32_t)(ks * 32);
            uint32_t ah0[4], ah1[4];
            ldsm4(ah0, aA0 + kb);
            ldsm4(ah1, aA0 + A_MB + kb);
#pragma unroll
            for (int np = 0; np < 2; np++) {
                uint32_t bh[4], bl[4];
                ldsm4(bh, aB0 + np * B_NP + kb);
                ldsm4(bl, aB0 + B_LO + np * B_NP + kb);
                float* d00 = acc + (0 * 4 + np * 2) * 4;
                float* d01 = acc + (0 * 4 + np * 2 + 1) * 4;
                float* d10 = acc + (1 * 4 + np * 2) * 4;
                float* d11 = acc + (1 * 4 + np * 2 + 1) * 4;
                mma_f16(d00, ah0, bh[0], bh[1]);
                mma_f16(d00, ah0, bl[0], bl[1]);
                mma_f16(d01, ah0, bh[2], bh[3]);
                mma_f16(d01, ah0, bl[2], bl[3]);
                mma_f16(d10, ah1, bh[0], bh[1]);
                mma_f16(d10, ah1, bl[0], bl[1]);
                mma_f16(d11, ah1, bh[2], bh[3]);
                mma_f16(d11, ah1, bl[2], bl[3]);
            }
        }

        // ---- Flush (x 2^-8 to undo weight scaling) ----
        int rq = lane >> 2;
        int cq = 2 * (lane & 3);
        const float SC = 0.00390625f;  // 2^-8
#pragma unroll
        for (int mb = 0; mb < 2; mb++) {
#pragma unroll
            for (int nb = 0; nb < 4; nb++) {
                float* d = acc + (mb * 4 + nb) * 4;
                int r0 = base + rg * 32 + mb * 16 + rq;
                int col = h * 64 + cg * 32 + nb * 8 + cq;
                if (col < NSELF) {
                    if (r0 < M)
                        *reinterpret_cast<float2*>(&Cself[(size_t)r0 * NSELF + col]) =
                            make_float2(d[0] * SC, d[1] * SC);
                    if (r0 + 8 < M)
                        *reinterpret_cast<float2*>(&Cself[(size_t)(r0 + 8) * NSELF + col]) =
                            make_float2(d[2] * SC, d[3] * SC);
                } else {
                    int pc = col - NSELF;
                    if (r0 < M)
                        *reinterpret_cast<__half2*>(&Pneigh[(size_t)r0 * NP + pc]) =
                            __floats2half2_rn(d[0] * SC, d[1] * SC);
                    if (r0 + 8 < M)
                        *reinterpret_cast<__half2*>(&Pneigh[(size_t)(r0 + 8) * NP + pc]) =
                            __floats2half2_rn(d[2] * SC, d[3] * SC);
                }
            }
        }
    }
}

// ---------------------------------------------------------------------------
// Layer-1 gather sums ONLY (no epilogue): warp per node, uint2, unroll 4.
// Writes raw fp32 sums to g_SUM1. Needs CSR + P1 (NOT C1s).
// ---------------------------------------------------------------------------
__global__ void agg_sum1_kernel() {
    int node = (blockIdx.x * blockDim.x + threadIdx.x) >> 5;
    int lane = threadIdx.x & 31;
    if (node >= NNODES) return;

    int beg = g_off[node];
    int cnt = g_cnt[node];
    int end = beg + cnt;

    const uint2* P = reinterpret_cast<const uint2*>(g_P1);
    float4 a0 = make_float4(0.f, 0.f, 0.f, 0.f);
    float4 a1 = a0, a2 = a0, a3 = a0;

    int j = beg;
    for (; j + 4 <= end; j += 4) {
        int s0 = g_csr[j];
        int s1 = g_csr[j + 1];
        int s2 = g_csr[j + 2];
        int s3 = g_csr[j + 3];
        a0 = f4addh(a0, P[(size_t)s0 * 32 + lane]);
        a1 = f4addh(a1, P[(size_t)s1 * 32 + lane]);
        a2 = f4addh(a2, P[(size_t)s2 * 32 + lane]);
        a3 = f4addh(a3, P[(size_t)s3 * 32 + lane]);
    }
    for (; j < end; j++) {
        int s = g_csr[j];
        a0 = f4addh(a0, P[(size_t)s * 32 + lane]);
    }
    g_SUM1[(size_t)node * 32 + lane] =
        f4add(f4add(a0, a1), f4add(a2, a3));
}

// ---------------------------------------------------------------------------
// Layer-1 epilogue: H1 = relu(C1s + SUM1/max(deg,1) + b1), fp16 out.
// Needs C1s (GEMM1s) + SUM1 (agg_sum1).
// ---------------------------------------------------------------------------
__global__ void fin1_kernel(const float* __restrict__ b1) {
    int idx = blockIdx.x * blockDim.x + threadIdx.x;  // over N*32 float4s
    if (idx >= NNODES * 32) return;
    int node = idx >> 5;
    int q = idx & 31;
    float rdeg = 1.0f / fmaxf((float)g_cnt[node], 1.0f);
    float4 self = reinterpret_cast<const float4*>(g_C1s)[idx];
    float4 sum = g_SUM1[idx];
    float4 bb = reinterpret_cast<const float4*>(b1)[q];
    float hx = fmaxf(fmaf(sum.x, rdeg, self.x) + bb.x, 0.f);
    float hy = fmaxf(fmaf(sum.y, rdeg, self.y) + bb.y, 0.f);
    float hz = fmaxf(fmaf(sum.z, rdeg, self.z) + bb.z, 0.f);
    float hw = fmaxf(fmaf(sum.w, rdeg, self.w) + bb.w, 0.f);
    __half2 p0 = __floats2half2_rn(hx, hy);
    __half2 p1 = __floats2half2_rn(hz, hw);
    uint2 st;
    st.x = *reinterpret_cast<uint32_t*>(&p0);
    st.y = *reinterpret_cast<uint32_t*>(&p1);
    *reinterpret_cast<uint2*>(&g_H1[(size_t)node * 128 + q * 4]) = st;
}

// ---------------------------------------------------------------------------
// Fused CSR aggregation + epilogue, layer 2 (unchanged).
// ---------------------------------------------------------------------------
__global__ void agg_fin2_kernel(const float* __restrict__ b2,
                                float4* __restrict__ out) {
    int grp = (blockIdx.x * blockDim.x + threadIdx.x) >> 4;
    int lane = threadIdx.x & 15;
    if (grp >= NNODES) return;
    int node = grp;

    int beg = g_off[node];
    int cnt = g_cnt[node];
    int end = beg + cnt;

    const uint2* P = reinterpret_cast<const uint2*>(g_P2);
    float4 a0 = make_float4(0.f, 0.f, 0.f, 0.f);
    float4 a1 = a0, a2 = a0, a3 = a0;

    int j = beg;
    for (; j + 4 <= end; j += 4) {
        int s0 = g_csr[j];
        int s1 = g_csr[j + 1];
        int s2 = g_csr[j + 2];
        int s3 = g_csr[j + 3];
        a0 = f4addh(a0, P[(size_t)s0 * 16 + lane]);
        a1 = f4addh(a1, P[(size_t)s1 * 16 + lane]);
        a2 = f4addh(a2, P[(size_t)s2 * 16 + lane]);
        a3 = f4addh(a3, P[(size_t)s3 * 16 + lane]);
    }
    for (; j < end; j++) {
        int s = g_csr[j];
        a0 = f4addh(a0, P[(size_t)s * 16 + lane]);
    }
    float4 sum = f4add(f4add(a0, a1), f4add(a2, a3));

    float rdeg = 1.0f / fmaxf((float)cnt, 1.0f);
    float4 self = reinterpret_cast<const float4*>(g_C2s)[node * 16 + lane];
    float4 bb = reinterpret_cast<const float4*>(b2)[lane];
    float4 o;
    o.x = fmaf(sum.x, rdeg, self.x) + bb.x;
    o.y = fmaf(sum.y, rdeg, self.y) + bb.y;
    o.z = fmaf(sum.z, rdeg, self.z) + bb.z;
    o.w = fmaf(sum.w, rdeg, self.w) + bb.w;
    out[node * 16 + lane] = o;
}

// ---------------------------------------------------------------------------
// Launch. Two-way overlap:
//   side:  CSR chain -> GEMM1s (C1s; needs prep only)
//   main:  prep -> GEMM1n (P1) -> [wait CSR] agg_sum1 (|| GEMM1s)
//          -> [wait GEMM1s] fin1 -> GEMM2 -> agg_fin2
// ---------------------------------------------------------------------------
extern "C" void kernel_launch(void* const* d_in, const int* in_sizes, int n_in,
                              void* d_out, int out_size) {
    const float* x   = (const float*)d_in[0];
    const float* Ws1 = (const float*)d_in[1];
    const float* Wn1 = (const float*)d_in[2];
    const float* b1  = (const float*)d_in[3];
    const float* Ws2 = (const float*)d_in[4];
    const float* Wn2 = (const float*)d_in[5];
    const float* b2  = (const float*)d_in[6];
    const int*   src = (const int*)d_in[7];
    const int*   dst = (const int*)d_in[8];
    float4* out = (float4*)d_out;

    float *c1s = nullptr, *c2s = nullptr;
    __half *p1 = nullptr, *p2 = nullptr, *h1 = nullptr;
    __half *w1h = nullptr, *w1l = nullptr, *w2h = nullptr, *w2l = nullptr;
    cudaGetSymbolAddress((void**)&c1s, g_C1s);
    cudaGetSymbolAddress((void**)&p1,  g_P1);
    cudaGetSymbolAddress((void**)&h1,  g_H1);
    cudaGetSymbolAddress((void**)&c2s, g_C2s);
    cudaGetSymbolAddress((void**)&p2,  g_P2);
    cudaGetSymbolAddress((void**)&w1h, g_W1H);
    cudaGetSymbolAddress((void**)&w1l, g_W1L);
    cudaGetSymbolAddress((void**)&w2h, g_W2H);
    cudaGetSymbolAddress((void**)&w2l, g_W2L);

    static cudaStream_t s_side = nullptr;
    static cudaEvent_t  s_fork = nullptr, e_prep = nullptr,
                        e_csr = nullptr, e_g1s = nullptr;
    if (s_side == nullptr) {
        cudaStreamCreateWithFlags(&s_side, cudaStreamNonBlocking);
        cudaEventCreateWithFlags(&s_fork, cudaEventDisableTiming);
        cudaEventCreateWithFlags(&e_prep, cudaEventDisableTiming);
        cudaEventCreateWithFlags(&e_csr,  cudaEventDisableTiming);
        cudaEventCreateWithFlags(&e_g1s,  cudaEventDisableTiming);
    }

    const int SCAN_BLOCKS = (NNODES + 511) / 512;            // 98
    const int GTILES = (NNODES + 127) / 128;                 // 391
    // SMEM: A fp16 128*136*2 + W hi/lo fp16 2*64*136*2 = 69632 bytes
    const int GSMEM = 128 * 136 * 2 + 2 * 64 * 136 * 2;

    cudaFuncSetAttribute((const void*)gemm_mma_kernel<128, 0, true>,
                         cudaFuncAttributeMaxDynamicSharedMemorySize, GSMEM);
    cudaFuncSetAttribute((const void*)gemm_mma_kernel<128, 128, true>,
                         cudaFuncAttributeMaxDynamicSharedMemorySize, GSMEM);
    cudaFuncSetAttribute((const void*)gemm_mma_kernel<128, 64, false>,
                         cudaFuncAttributeMaxDynamicSharedMemorySize, GSMEM);

    // ---- Fork ----
    cudaEventRecord(s_fork, 0);
    cudaStreamWaitEvent(s_side, s_fork, 0);

    // Side: CSR chain start
    zero_cnt_kernel<<<(NNODES + 255) / 256, 256, 0, s_side>>>();
    hist_kernel<<<(NEDGES + 255) / 256, 256, 0, s_side>>>(dst);

    // Main: weight prep, then neighbor-half GEMM1 (launch #4 for ncu)
    prep_w_kernel<<<128, 256>>>(Ws1, Wn1, Ws2, Wn2);
    cudaEventRecord(e_prep, 0);
    gemm_mma_kernel<128, 0, true><<<GTILES, 256, GSMEM>>>(
        (const void*)x, w1h + 128 * 128, w1l + 128 * 128, c1s /*unused*/, p1, NNODES);

    // Side: rest of CSR, then self-half GEMM1 (needs prep)
    scanA_kernel<<<SCAN_BLOCKS, 512, 0, s_side>>>();
    scanC_kernel<<<(NNODES + 255) / 256, 256, 0, s_side>>>(SCAN_BLOCKS);
    scatter_kernel<<<(NEDGES + 255) / 256, 256, 0, s_side>>>(src, dst);
    cudaEventRecord(e_csr, s_side);
    cudaStreamWaitEvent(s_side, e_prep, 0);
    gemm_mma_kernel<128, 128, true><<<GTILES, 256, GSMEM, s_side>>>(
        (const void*)x, w1h, w1l, c1s, p1 /*unused*/, NNODES);
    cudaEventRecord(e_g1s, s_side);

    // Main: gather sums (needs CSR + P1), concurrent with GEMM1s
    cudaStreamWaitEvent(0, e_csr, 0);
    agg_sum1_kernel<<<(NNODES * 32 + 255) / 256, 256>>>();

    // Main: epilogue (needs C1s), then layer 2
    cudaStreamWaitEvent(0, e_g1s, 0);
    fin1_kernel<<<(NNODES * 32 + 255) / 256, 256>>>(b1);

    gemm_mma_kernel<128, 64, false><<<GTILES, 256, GSMEM>>>(
        (const void*)h1, w2h, w2l, c2s, p2, NNODES);
    agg_fin2_kernel<<<(NNODES * 16 + 255) / 256, 256>>>(b2, out);
}

// round 16
// speedup vs baseline: 1.2046x; 1.2046x over previous
#include <cuda_runtime.h>
#include <cuda_bf16.h>
#include <cuda_fp16.h>
#include <cstdint>

// Problem constants (match reference setup_inputs)
#define NNODES 50000
#define NEDGES 640000
// IN_DIM = 128, HID = 128, OUT = 64

// ---------------------------------------------------------------------------
// Device scratch (allocation-free rule: __device__ globals)
// ---------------------------------------------------------------------------
__device__ __half g_X16[NNODES * 128];    // x pre-converted to fp16
__device__ float  g_C1s[NNODES * 128];    // layer1 self projection (fp32)
__device__ __half g_P1[NNODES * 128];     // layer1 neighbor projection (fp16)
__device__ __half g_H1[NNODES * 128];     // hidden activations (fp16)
__device__ float  g_C2s[NNODES * 64];     // layer2 self projection (fp32)
__device__ __half g_P2[NNODES * 64];      // layer2 neighbor projection (fp16)
// fp16 hi/lo split weights, SCALED BY 256, plain [n][k] row-major
__device__ __align__(16) __half g_W1H[256 * 128];
__device__ __align__(16) __half g_W1L[256 * 128];
__device__ __align__(16) __half g_W2H[128 * 128];
__device__ __align__(16) __half g_W2L[128 * 128];
// CSR build scratch
__device__ int    g_cnt[NNODES];
__device__ int    g_off[NNODES];
__device__ int    g_cur[NNODES];
__device__ int    g_csr[NEDGES];
__device__ int    g_blkSums[128];

// ---------------------------------------------------------------------------
// Helpers
// ---------------------------------------------------------------------------
__device__ __forceinline__ uint32_t smem_u32(const void* p) {
    uint32_t a;
    asm("{ .reg .u64 t; cvta.to.shared.u64 t, %1; cvt.u32.u64 %0, t; }"
        : "=r"(a) : "l"(p));
    return a;
}
__device__ __forceinline__ void ldsm4(uint32_t* r, uint32_t addr) {
    asm volatile("ldmatrix.sync.aligned.m8n8.x4.shared.b16 {%0,%1,%2,%3}, [%4];"
                 : "=r"(r[0]), "=r"(r[1]), "=r"(r[2]), "=r"(r[3]) : "r"(addr));
}
__device__ __forceinline__ void mma_f16(float* d, const uint32_t* a,
                                        uint32_t b0, uint32_t b1) {
    asm volatile(
        "mma.sync.aligned.m16n8k16.row.col.f32.f16.f16.f32 "
        "{%0,%1,%2,%3}, {%4,%5,%6,%7}, {%8,%9}, {%0,%1,%2,%3};"
        : "+f"(d[0]), "+f"(d[1]), "+f"(d[2]), "+f"(d[3])
        : "r"(a[0]), "r"(a[1]), "r"(a[2]), "r"(a[3]), "r"(b0), "r"(b1));
}
__device__ __forceinline__ float4 f4add(float4 a, float4 b) {
    return make_float4(a.x + b.x, a.y + b.y, a.z + b.z, a.w + b.w);
}
// Accumulate 4 fp16 values (as uint2) into a float4
__device__ __forceinline__ float4 f4addh(float4 a, uint2 v) {
    __half2 p0 = *reinterpret_cast<__half2*>(&v.x);
    __half2 p1 = *reinterpret_cast<__half2*>(&v.y);
    float2 f0 = __half22float2(p0);
    float2 f1 = __half22float2(p1);
    return make_float4(a.x + f0.x, a.y + f0.y, a.z + f1.x, a.w + f1.y);
}

// ---------------------------------------------------------------------------
// x -> fp16 pre-convert (grid-stride, float4 -> half4)
// ---------------------------------------------------------------------------
__global__ void x2h_kernel(const float* __restrict__ x) {
    int i = blockIdx.x * blockDim.x + threadIdx.x;
    int stride = gridDim.x * blockDim.x;
    const float4* X4 = reinterpret_cast<const float4*>(x);
    uint2* O = reinterpret_cast<uint2*>(g_X16);
    for (; i < NNODES * 32; i += stride) {
        float4 v = X4[i];
        __half2 p0 = __floats2half2_rn(v.x, v.y);
        __half2 p1 = __floats2half2_rn(v.z, v.w);
        uint2 st;
        st.x = *reinterpret_cast<uint32_t*>(&p0);
        st.y = *reinterpret_cast<uint32_t*>(&p1);
        O[i] = st;
    }
}

// ---------------------------------------------------------------------------
// CSR build: zero counts -> histogram -> scanA -> scanC(+parallel prefix) -> scatter
// ---------------------------------------------------------------------------
__global__ void zero_cnt_kernel() {
    int i = blockIdx.x * blockDim.x + threadIdx.x;
    if (i < NNODES) g_cnt[i] = 0;
}
__global__ void hist_kernel(const int* __restrict__ dst) {
    int e = blockIdx.x * blockDim.x + threadIdx.x;
    if (e < NEDGES) atomicAdd(&g_cnt[dst[e]], 1);
}
__global__ void scanA_kernel() {
    __shared__ int s[512];
    int b = blockIdx.x, t = threadIdx.x;
    int i = b * 512 + t;
    int v = (i < NNODES) ? g_cnt[i] : 0;
    s[t] = v;
    __syncthreads();
#pragma unroll
    for (int d = 1; d < 512; d <<= 1) {
        int x = (t >= d) ? s[t - d] : 0;
        __syncthreads();
        s[t] += x;
        __syncthreads();
    }
    if (i < NNODES) g_off[i] = s[t] - v;
    if (t == 511) g_blkSums[b] = s[t];
}
__global__ void scanC_kernel(int nblocks) {
    __shared__ int s[128];
    int t = threadIdx.x;
    if (t < 128) s[t] = (t < nblocks) ? g_blkSums[t] : 0;
    __syncthreads();
#pragma unroll
    for (int d = 1; d < 128; d <<= 1) {
        int x = 0;
        if (t < 128 && t >= d) x = s[t - d];
        __syncthreads();
        if (t < 128) s[t] += x;
        __syncthreads();
    }
    int i = blockIdx.x * blockDim.x + t;
    if (i < NNODES) {
        int blk = i >> 9;
        int pre = (blk == 0) ? 0 : s[blk - 1];
        int o = g_off[i] + pre;
        g_off[i] = o;
        g_cur[i] = o;
    }
}
__global__ void scatter_kernel(const int* __restrict__ src,
                               const int* __restrict__ dst) {
    int e = blockIdx.x * blockDim.x + threadIdx.x;
    if (e < NEDGES) {
        int d = dst[e];
        int p = atomicAdd(&g_cur[d], 1);
        g_csr[p] = src[e];
    }
}

// ---------------------------------------------------------------------------
// Weight prep: split fp32 -> fp16 hi/lo SCALED BY 256, plain [n][k] layout.
// ---------------------------------------------------------------------------
__global__ void prep_w_kernel(const float* __restrict__ Ws1,
                              const float* __restrict__ Wn1,
                              const float* __restrict__ Ws2,
                              const float* __restrict__ Wn2) {
    int i = blockIdx.x * blockDim.x + threadIdx.x;
    if (i < 256 * 128) {
        int n = i >> 7, k = i & 127;
        float w = (n < 128) ? Ws1[n * 128 + k] : Wn1[(n - 128) * 128 + k];
        float ws = w * 256.0f;
        __half h = __float2half_rn(ws);
        g_W1H[i] = h;
        g_W1L[i] = __float2half_rn(ws - __half2float(h));
    }
    if (i < 128 * 128) {
        int n = i >> 7, k = i & 127;
        float w = (n < 64) ? Ws2[n * 128 + k] : Wn2[(n - 64) * 128 + k];
        float ws = w * 256.0f;
        __half h = __float2half_rn(ws);
        g_W2H[i] = h;
        g_W2L[i] = __float2half_rn(ws - __half2float(h));
    }
}

// ---------------------------------------------------------------------------
// Tensor-core GEMM via mma.sync (HMMA fp16, fp32 accum), 2-term W split:
//   D = A_fp16 * (Wh + Wl) * 2^-8
// CTA = 256 threads (8 warps), CTA tile 128 rows x 64-col W strip.
// Warp tile = 32 rows x 32 cols. A is fp16 in gmem (straight uint4 copy).
// SMEM: A[128][136] + WH[64][136] + WL[64][136] fp16 = 69632 B
//   -> 3 CTAs/SM -> 24 warps/SM.
// Cols [0, NSELF) -> fp32 Cself; cols [NSELF, NOUT) -> fp16 Pneigh.
// ---------------------------------------------------------------------------
template <int NOUT, int NSELF>
__global__ void __launch_bounds__(256, 3)
gemm_mma_kernel(const __half* __restrict__ Asrc,
                const __half* __restrict__ WHg,
                const __half* __restrict__ WLg,
                float* __restrict__ Cself,
                __half* __restrict__ Pneigh, int M) {
    constexpr int ASTR = 136;
    constexpr int WSTR = 136;
    constexpr int NP = NOUT - NSELF;
    extern __shared__ __half smem[];
    __half* sA  = smem;                    // 128*136 fp16
    __half* sWH = sA + 128 * ASTR;         // 64*136
    __half* sWL = sWH + 64 * WSTR;

    int tid = threadIdx.x;
    int warp = tid >> 5, lane = tid & 31;
    int rg = warp >> 1;                    // row group of 32 (0..3)
    int cg = warp & 1;                     // col group of 32 (0..1)
    int base = blockIdx.x * 128;

    // ---- Load A tile (128 rows x 128 fp16): straight uint4 copies ----
    {
        int row = tid >> 1;
        int cbase = (tid & 1) * 64;
        int grow = base + row;
        const uint4* A4 = reinterpret_cast<const uint4*>(Asrc);  // 8 halves each
#pragma unroll
        for (int i = 0; i < 8; i++) {
            uint4 u;
            if (grow < M) u = A4[(size_t)grow * 16 + (cbase >> 3) + i];
            else          u = make_uint4(0, 0, 0, 0);
            int off = row * ASTR + cbase + 8 * i;
            *reinterpret_cast<uint4*>(sA + off) = u;
        }
    }

    // Per-thread ldmatrix base offsets
    int g8 = lane >> 3, j8 = lane & 7;
    uint32_t aA0 = smem_u32(sA) +
                   (uint32_t)(((rg * 32 + (g8 & 1) * 8 + j8) * ASTR + (g8 >> 1) * 8) * 2);
    constexpr uint32_t A_MB = 16u * ASTR * 2u;        // m-block stride
    uint32_t aB0 = smem_u32(sWH) +
                   (uint32_t)(((cg * 32 + (g8 >> 1) * 8 + j8) * WSTR + (g8 & 1) * 8) * 2);
    constexpr uint32_t B_NP = 16u * WSTR * 2u;        // nblk-pair stride
    constexpr uint32_t B_LO = 64u * WSTR * 2u;        // hi->lo plane

#pragma unroll
    for (int h = 0; h < NOUT / 64; h++) {
        __syncthreads();
        // ---- Load W strip (64 cols x 128 k) hi/lo fp16 ----
        {
            int n = tid >> 2;
            int q4 = (tid & 3) * 4;
            const uint4* gh = reinterpret_cast<const uint4*>(WHg) +
                              (size_t)(h * 64 + n) * 16 + q4;
            const uint4* gl = reinterpret_cast<const uint4*>(WLg) +
                              (size_t)(h * 64 + n) * 16 + q4;
            uint4* sh = reinterpret_cast<uint4*>(sWH + n * WSTR) + q4;
            uint4* sl = reinterpret_cast<uint4*>(sWL + n * WSTR) + q4;
#pragma unroll
            for (int i = 0; i < 4; i++) {
                sh[i] = gh[i];
                sl[i] = gl[i];
            }
        }
        __syncthreads();

        float acc[32];
#pragma unroll
        for (int i = 0; i < 32; i++) acc[i] = 0.f;

#pragma unroll
        for (int ks = 0; ks < 8; ks++) {
            uint32_t kb = (uint32_t)(ks * 32);
            uint32_t ah0[4], ah1[4];
            ldsm4(ah0, aA0 + kb);
            ldsm4(ah1, aA0 + A_MB + kb);
#pragma unroll
            for (int np = 0; np < 2; np++) {
                uint32_t bh[4], bl[4];
                ldsm4(bh, aB0 + np * B_NP + kb);
                ldsm4(bl, aB0 + B_LO + np * B_NP + kb);
                float* d00 = acc + (0 * 4 + np * 2) * 4;
                float* d01 = acc + (0 * 4 + np * 2 + 1) * 4;
                float* d10 = acc + (1 * 4 + np * 2) * 4;
                float* d11 = acc + (1 * 4 + np * 2 + 1) * 4;
                mma_f16(d00, ah0, bh[0], bh[1]);
                mma_f16(d00, ah0, bl[0], bl[1]);
                mma_f16(d01, ah0, bh[2], bh[3]);
                mma_f16(d01, ah0, bl[2], bl[3]);
                mma_f16(d10, ah1, bh[0], bh[1]);
                mma_f16(d10, ah1, bl[0], bl[1]);
                mma_f16(d11, ah1, bh[2], bh[3]);
                mma_f16(d11, ah1, bl[2], bl[3]);
            }
        }

        // ---- Flush (x 2^-8 to undo weight scaling) ----
        int rq = lane >> 2;
        int cq = 2 * (lane & 3);
        const float SC = 0.00390625f;  // 2^-8
#pragma unroll
        for (int mb = 0; mb < 2; mb++) {
#pragma unroll
            for (int nb = 0; nb < 4; nb++) {
                float* d = acc + (mb * 4 + nb) * 4;
                int r0 = base + rg * 32 + mb * 16 + rq;
                int col = h * 64 + cg * 32 + nb * 8 + cq;
                if (col < NSELF) {
                    if (r0 < M)
                        *reinterpret_cast<float2*>(&Cself[(size_t)r0 * NSELF + col]) =
                            make_float2(d[0] * SC, d[1] * SC);
                    if (r0 + 8 < M)
                        *reinterpret_cast<float2*>(&Cself[(size_t)(r0 + 8) * NSELF + col]) =
                            make_float2(d[2] * SC, d[3] * SC);
                } else {
                    int pc = col - NSELF;
                    if (r0 < M)
                        *reinterpret_cast<__half2*>(&Pneigh[(size_t)r0 * NP + pc]) =
                            __floats2half2_rn(d[0] * SC, d[1] * SC);
                    if (r0 + 8 < M)
                        *reinterpret_cast<__half2*>(&Pneigh[(size_t)(r0 + 8) * NP + pc]) =
                            __floats2half2_rn(d[2] * SC, d[3] * SC);
                }
            }
        }
    }
}

// ---------------------------------------------------------------------------
// Fused CSR aggregation + epilogue, layer 1 (round-13 exact).
// Warp per node: 32 lanes x 4 halves (uint2). Unroll 4. H1 written as fp16.
// ---------------------------------------------------------------------------
__global__ void agg_fin1_kernel(const float* __restrict__ b1) {
    int node = (blockIdx.x * blockDim.x + threadIdx.x) >> 5;
    int lane = threadIdx.x & 31;
    if (node >= NNODES) return;

    int beg = g_off[node];
    int cnt = g_cnt[node];
    int end = beg + cnt;

    const uint2* P = reinterpret_cast<const uint2*>(g_P1);
    float4 a0 = make_float4(0.f, 0.f, 0.f, 0.f);
    float4 a1 = a0, a2 = a0, a3 = a0;

    int j = beg;
    for (; j + 4 <= end; j += 4) {
        int s0 = g_csr[j];
        int s1 = g_csr[j + 1];
        int s2 = g_csr[j + 2];
        int s3 = g_csr[j + 3];
        a0 = f4addh(a0, P[(size_t)s0 * 32 + lane]);
        a1 = f4addh(a1, P[(size_t)s1 * 32 + lane]);
        a2 = f4addh(a2, P[(size_t)s2 * 32 + lane]);
        a3 = f4addh(a3, P[(size_t)s3 * 32 + lane]);
    }
    for (; j < end; j++) {
        int s = g_csr[j];
        a0 = f4addh(a0, P[(size_t)s * 32 + lane]);
    }
    float4 sum = f4add(f4add(a0, a1), f4add(a2, a3));

    float rdeg = 1.0f / fmaxf((float)cnt, 1.0f);
    float4 self = reinterpret_cast<const float4*>(g_C1s)[node * 32 + lane];
    float4 bb = reinterpret_cast<const float4*>(b1)[lane];
    float hx = fmaxf(fmaf(sum.x, rdeg, self.x) + bb.x, 0.f);
    float hy = fmaxf(fmaf(sum.y, rdeg, self.y) + bb.y, 0.f);
    float hz = fmaxf(fmaf(sum.z, rdeg, self.z) + bb.z, 0.f);
    float hw = fmaxf(fmaf(sum.w, rdeg, self.w) + bb.w, 0.f);
    __half2 p0 = __floats2half2_rn(hx, hy);
    __half2 p1 = __floats2half2_rn(hz, hw);
    uint2 st;
    st.x = *reinterpret_cast<uint32_t*>(&p0);
    st.y = *reinterpret_cast<uint32_t*>(&p1);
    *reinterpret_cast<uint2*>(&g_H1[(size_t)node * 128 + lane * 4]) = st;
}

// ---------------------------------------------------------------------------
// Fused CSR aggregation + epilogue, layer 2 (round-13 exact).
// ---------------------------------------------------------------------------
__global__ void agg_fin2_kernel(const float* __restrict__ b2,
                                float4* __restrict__ out) {
    int grp = (blockIdx.x * blockDim.x + threadIdx.x) >> 4;
    int lane = threadIdx.x & 15;
    if (grp >= NNODES) return;
    int node = grp;

    int beg = g_off[node];
    int cnt = g_cnt[node];
    int end = beg + cnt;

    const uint2* P = reinterpret_cast<const uint2*>(g_P2);
    float4 a0 = make_float4(0.f, 0.f, 0.f, 0.f);
    float4 a1 = a0, a2 = a0, a3 = a0;

    int j = beg;
    for (; j + 4 <= end; j += 4) {
        int s0 = g_csr[j];
        int s1 = g_csr[j + 1];
        int s2 = g_csr[j + 2];
        int s3 = g_csr[j + 3];
        a0 = f4addh(a0, P[(size_t)s0 * 16 + lane]);
        a1 = f4addh(a1, P[(size_t)s1 * 16 + lane]);
        a2 = f4addh(a2, P[(size_t)s2 * 16 + lane]);
        a3 = f4addh(a3, P[(size_t)s3 * 16 + lane]);
    }
    for (; j < end; j++) {
        int s = g_csr[j];
        a0 = f4addh(a0, P[(size_t)s * 16 + lane]);
    }
    float4 sum = f4add(f4add(a0, a1), f4add(a2, a3));

    float rdeg = 1.0f / fmaxf((float)cnt, 1.0f);
    float4 self = reinterpret_cast<const float4*>(g_C2s)[node * 16 + lane];
    float4 bb = reinterpret_cast<const float4*>(b2)[lane];
    float4 o;
    o.x = fmaf(sum.x, rdeg, self.x) + bb.x;
    o.y = fmaf(sum.y, rdeg, self.y) + bb.y;
    o.z = fmaf(sum.z, rdeg, self.z) + bb.z;
    o.w = fmaf(sum.w, rdeg, self.w) + bb.w;
    out[node * 16 + lane] = o;
}

// ---------------------------------------------------------------------------
// Launch (round-13 schedule + x2h). CSR on side stream overlapped with
// prep_w + x2h + GEMM1 on main. gemm1 stays launch #4 for ncu.
// ---------------------------------------------------------------------------
extern "C" void kernel_launch(void* const* d_in, const int* in_sizes, int n_in,
                              void* d_out, int out_size) {
    const float* x   = (const float*)d_in[0];
    const float* Ws1 = (const float*)d_in[1];
    const float* Wn1 = (const float*)d_in[2];
    const float* b1  = (const float*)d_in[3];
    const float* Ws2 = (const float*)d_in[4];
    const float* Wn2 = (const float*)d_in[5];
    const float* b2  = (const float*)d_in[6];
    const int*   src = (const int*)d_in[7];
    const int*   dst = (const int*)d_in[8];
    float4* out = (float4*)d_out;

    float *c1s = nullptr, *c2s = nullptr;
    __half *p1 = nullptr, *p2 = nullptr, *h1 = nullptr, *x16 = nullptr;
    __half *w1h = nullptr, *w1l = nullptr, *w2h = nullptr, *w2l = nullptr;
    cudaGetSymbolAddress((void**)&x16, g_X16);
    cudaGetSymbolAddress((void**)&c1s, g_C1s);
    cudaGetSymbolAddress((void**)&p1,  g_P1);
    cudaGetSymbolAddress((void**)&h1,  g_H1);
    cudaGetSymbolAddress((void**)&c2s, g_C2s);
    cudaGetSymbolAddress((void**)&p2,  g_P2);
    cudaGetSymbolAddress((void**)&w1h, g_W1H);
    cudaGetSymbolAddress((void**)&w1l, g_W1L);
    cudaGetSymbolAddress((void**)&w2h, g_W2H);
    cudaGetSymbolAddress((void**)&w2l, g_W2L);

    static cudaStream_t s_side = nullptr;
    static cudaEvent_t  s_fork = nullptr, s_join = nullptr;
    if (s_side == nullptr) {
        cudaStreamCreateWithFlags(&s_side, cudaStreamNonBlocking);
        cudaEventCreateWithFlags(&s_fork, cudaEventDisableTiming);
        cudaEventCreateWithFlags(&s_join, cudaEventDisableTiming);
    }

    const int SCAN_BLOCKS = (NNODES + 511) / 512;            // 98
    const int GTILES = (NNODES + 127) / 128;                 // 391
    // SMEM: A fp16 128*136*2 + W hi/lo fp16 2*64*136*2 = 69632 bytes
    const int GSMEM = 128 * 136 * 2 + 2 * 64 * 136 * 2;

    cudaFuncSetAttribute((const void*)gemm_mma_kernel<256, 128>,
                         cudaFuncAttributeMaxDynamicSharedMemorySize, GSMEM);
    cudaFuncSetAttribute((const void*)gemm_mma_kernel<128, 64>,
                         cudaFuncAttributeMaxDynamicSharedMemorySize, GSMEM);

    // ---- Fork ----
    cudaEventRecord(s_fork, 0);
    cudaStreamWaitEvent(s_side, s_fork, 0);

    // Launches #1-#3: prep_w + x2h (main), zero (side)
    prep_w_kernel<<<128, 256>>>(Ws1, Wn1, Ws2, Wn2);
    x2h_kernel<<<1024, 256>>>(x);
    zero_cnt_kernel<<<(NNODES + 255) / 256, 256, 0, s_side>>>();

    // Launch #4: GEMM1 (ncu target)
    gemm_mma_kernel<256, 128><<<GTILES, 256, GSMEM>>>(
        x16, w1h, w1l, c1s, p1, NNODES);

    // Launches #5-#8: rest of CSR chain (side stream)
    hist_kernel<<<(NEDGES + 255) / 256, 256, 0, s_side>>>(dst);
    scanA_kernel<<<SCAN_BLOCKS, 512, 0, s_side>>>();
    scanC_kernel<<<(NNODES + 255) / 256, 256, 0, s_side>>>(SCAN_BLOCKS);
    scatter_kernel<<<(NEDGES + 255) / 256, 256, 0, s_side>>>(src, dst);
    cudaEventRecord(s_join, s_side);

    // ---- Join: aggregation needs CSR ----
    cudaStreamWaitEvent(0, s_join, 0);
    agg_fin1_kernel<<<(NNODES * 32 + 255) / 256, 256>>>(b1);

    gemm_mma_kernel<128, 64><<<GTILES, 256, GSMEM>>>(
        h1, w2h, w2l, c2s, p2, NNODES);
    agg_fin2_kernel<<<(NNODES * 16 + 255) / 256, 256>>>(b2, out);
}

// round 17
// speedup vs baseline: 1.4009x; 1.1630x over previous
#include <cuda_runtime.h>
#include <cuda_bf16.h>
#include <cuda_fp16.h>
#include <cstdint>

// Problem constants (match reference setup_inputs)
#define NNODES 50000
#define NEDGES 640000
// IN_DIM = 128, HID = 128, OUT = 64

// ---------------------------------------------------------------------------
// Device scratch (allocation-free rule: __device__ globals)
// ---------------------------------------------------------------------------
__device__ __half g_X16[NNODES * 128];    // x pre-converted to fp16
__device__ float  g_C1s[NNODES * 128];    // layer1 self projection (fp32)
__device__ __half g_P1[NNODES * 128];     // layer1 neighbor projection (fp16)
__device__ __half g_H1[NNODES * 128];     // hidden activations (fp16)
__device__ float  g_C2s[NNODES * 64];     // layer2 self projection (fp32)
__device__ __half g_P2[NNODES * 64];      // layer2 neighbor projection (fp16)
// Plain fp16 weights (single plane), [n][k] row-major (k contiguous)
__device__ __align__(16) __half g_W1[256 * 128];
__device__ __align__(16) __half g_W2[128 * 128];
// CSR build scratch
__device__ int    g_cnt[NNODES];
__device__ int    g_off[NNODES];
__device__ int    g_cur[NNODES];
__device__ int    g_csr[NEDGES];
__device__ int    g_blkSums[128];

// ---------------------------------------------------------------------------
// Helpers
// ---------------------------------------------------------------------------
__device__ __forceinline__ uint32_t smem_u32(const void* p) {
    uint32_t a;
    asm("{ .reg .u64 t; cvta.to.shared.u64 t, %1; cvt.u32.u64 %0, t; }"
        : "=r"(a) : "l"(p));
    return a;
}
__device__ __forceinline__ void ldsm4(uint32_t* r, uint32_t addr) {
    asm volatile("ldmatrix.sync.aligned.m8n8.x4.shared.b16 {%0,%1,%2,%3}, [%4];"
                 : "=r"(r[0]), "=r"(r[1]), "=r"(r[2]), "=r"(r[3]) : "r"(addr));
}
__device__ __forceinline__ void mma_f16(float* d, const uint32_t* a,
                                        uint32_t b0, uint32_t b1) {
    asm volatile(
        "mma.sync.aligned.m16n8k16.row.col.f32.f16.f16.f32 "
        "{%0,%1,%2,%3}, {%4,%5,%6,%7}, {%8,%9}, {%0,%1,%2,%3};"
        : "+f"(d[0]), "+f"(d[1]), "+f"(d[2]), "+f"(d[3])
        : "r"(a[0]), "r"(a[1]), "r"(a[2]), "r"(a[3]), "r"(b0), "r"(b1));
}
__device__ __forceinline__ float4 f4add(float4 a, float4 b) {
    return make_float4(a.x + b.x, a.y + b.y, a.z + b.z, a.w + b.w);
}
// Accumulate 4 fp16 values (as uint2) into a float4
__device__ __forceinline__ float4 f4addh(float4 a, uint2 v) {
    __half2 p0 = *reinterpret_cast<__half2*>(&v.x);
    __half2 p1 = *reinterpret_cast<__half2*>(&v.y);
    float2 f0 = __half22float2(p0);
    float2 f1 = __half22float2(p1);
    return make_float4(a.x + f0.x, a.y + f0.y, a.z + f1.x, a.w + f1.y);
}

// ---------------------------------------------------------------------------
// Fused prep: x -> fp16 AND weights -> fp16 (grid-stride loops)
// ---------------------------------------------------------------------------
__global__ void prep_kernel(const float* __restrict__ x,
                            const float* __restrict__ Ws1,
                            const float* __restrict__ Wn1,
                            const float* __restrict__ Ws2,
                            const float* __restrict__ Wn2) {
    int tid0 = blockIdx.x * blockDim.x + threadIdx.x;
    int stride = gridDim.x * blockDim.x;

    // x -> fp16 (float4 -> half4), N*32 float4s
    const float4* X4 = reinterpret_cast<const float4*>(x);
    uint2* O = reinterpret_cast<uint2*>(g_X16);
    for (int i = tid0; i < NNODES * 32; i += stride) {
        float4 v = X4[i];
        __half2 p0 = __floats2half2_rn(v.x, v.y);
        __half2 p1 = __floats2half2_rn(v.z, v.w);
        uint2 st;
        st.x = *reinterpret_cast<uint32_t*>(&p0);
        st.y = *reinterpret_cast<uint32_t*>(&p1);
        O[i] = st;
    }

    // W1 concat [256,128] -> fp16
    for (int i = tid0; i < 256 * 128; i += stride) {
        int n = i >> 7, k = i & 127;
        float w = (n < 128) ? Ws1[n * 128 + k] : Wn1[(n - 128) * 128 + k];
        g_W1[i] = __float2half_rn(w);
    }
    // W2 concat [128,128] -> fp16
    for (int i = tid0; i < 128 * 128; i += stride) {
        int n = i >> 7, k = i & 127;
        float w = (n < 64) ? Ws2[n * 128 + k] : Wn2[(n - 64) * 128 + k];
        g_W2[i] = __float2half_rn(w);
    }
}

// ---------------------------------------------------------------------------
// CSR build: zero counts -> histogram -> scanA -> scanC(+parallel prefix) -> scatter
// ---------------------------------------------------------------------------
__global__ void zero_cnt_kernel() {
    int i = blockIdx.x * blockDim.x + threadIdx.x;
    if (i < NNODES) g_cnt[i] = 0;
}
__global__ void hist_kernel(const int* __restrict__ dst) {
    int e = blockIdx.x * blockDim.x + threadIdx.x;
    if (e < NEDGES) atomicAdd(&g_cnt[dst[e]], 1);
}
__global__ void scanA_kernel() {
    __shared__ int s[512];
    int b = blockIdx.x, t = threadIdx.x;
    int i = b * 512 + t;
    int v = (i < NNODES) ? g_cnt[i] : 0;
    s[t] = v;
    __syncthreads();
#pragma unroll
    for (int d = 1; d < 512; d <<= 1) {
        int x = (t >= d) ? s[t - d] : 0;
        __syncthreads();
        s[t] += x;
        __syncthreads();
    }
    if (i < NNODES) g_off[i] = s[t] - v;
    if (t == 511) g_blkSums[b] = s[t];
}
__global__ void scanC_kernel(int nblocks) {
    __shared__ int s[128];
    int t = threadIdx.x;
    if (t < 128) s[t] = (t < nblocks) ? g_blkSums[t] : 0;
    __syncthreads();
#pragma unroll
    for (int d = 1; d < 128; d <<= 1) {
        int x = 0;
        if (t < 128 && t >= d) x = s[t - d];
        __syncthreads();
        if (t < 128) s[t] += x;
        __syncthreads();
    }
    int i = blockIdx.x * blockDim.x + t;
    if (i < NNODES) {
        int blk = i >> 9;
        int pre = (blk == 0) ? 0 : s[blk - 1];
        int o = g_off[i] + pre;
        g_off[i] = o;
        g_cur[i] = o;
    }
}
__global__ void scatter_kernel(const int* __restrict__ src,
                               const int* __restrict__ dst) {
    int e = blockIdx.x * blockDim.x + threadIdx.x;
    if (e < NEDGES) {
        int d = dst[e];
        int p = atomicAdd(&g_cur[d], 1);
        g_csr[p] = src[e];
    }
}

// ---------------------------------------------------------------------------
// Tensor-core GEMM via mma.sync (HMMA fp16, fp32 accum), single-plane W:
//   D = A_fp16 * W_fp16
// CTA = 256 threads (8 warps), CTA tile 128 rows x 64-col W strip.
// Warp tile = 32 rows x 32 cols. Per k16 per warp: 2 A-ldsm + 2 B-ldsm, 8 MMA.
// SMEM: A[128][136] + W[64][136] fp16 = 52224 B -> 3 CTAs/SM (24 warps).
// Cols [0, NSELF) -> fp32 Cself; cols [NSELF, NOUT) -> fp16 Pneigh.
// ---------------------------------------------------------------------------
template <int NOUT, int NSELF>
__global__ void __launch_bounds__(256, 3)
gemm_mma_kernel(const __half* __restrict__ Asrc,
                const __half* __restrict__ Wg,
                float* __restrict__ Cself,
                __half* __restrict__ Pneigh, int M) {
    constexpr int ASTR = 136;
    constexpr int WSTR = 136;
    constexpr int NP = NOUT - NSELF;
    extern __shared__ __half smem[];
    __half* sA = smem;                     // 128*136 fp16
    __half* sW = sA + 128 * ASTR;          // 64*136 fp16

    int tid = threadIdx.x;
    int warp = tid >> 5, lane = tid & 31;
    int rg = warp >> 1;                    // row group of 32 (0..3)
    int cg = warp & 1;                     // col group of 32 (0..1)
    int base = blockIdx.x * 128;

    // ---- Load A tile (128 rows x 128 fp16): straight uint4 copies ----
    {
        int row = tid >> 1;
        int cbase = (tid & 1) * 64;
        int grow = base + row;
        const uint4* A4 = reinterpret_cast<const uint4*>(Asrc);  // 8 halves each
#pragma unroll
        for (int i = 0; i < 8; i++) {
            uint4 u;
            if (grow < M) u = A4[(size_t)grow * 16 + (cbase >> 3) + i];
            else          u = make_uint4(0, 0, 0, 0);
            int off = row * ASTR + cbase + 8 * i;
            *reinterpret_cast<uint4*>(sA + off) = u;
        }
    }

    // Per-thread ldmatrix base offsets
    int g8 = lane >> 3, j8 = lane & 7;
    uint32_t aA0 = smem_u32(sA) +
                   (uint32_t)(((rg * 32 + (g8 & 1) * 8 + j8) * ASTR + (g8 >> 1) * 8) * 2);
    constexpr uint32_t A_MB = 16u * ASTR * 2u;        // m-block stride
    uint32_t aB0 = smem_u32(sW) +
                   (uint32_t)(((cg * 32 + (g8 >> 1) * 8 + j8) * WSTR + (g8 & 1) * 8) * 2);
    constexpr uint32_t B_NP = 16u * WSTR * 2u;        // nblk-pair stride

#pragma unroll
    for (int h = 0; h < NOUT / 64; h++) {
        // Covers initial A stores (h=0) and previous strip's W reads (h>0)
        __syncthreads();
        // ---- Load W strip (64 cols x 128 k) fp16 ----
        {
            int n = tid >> 2;
            int q4 = (tid & 3) * 4;
            const uint4* gw = reinterpret_cast<const uint4*>(Wg) +
                              (size_t)(h * 64 + n) * 16 + q4;
            uint4* sw = reinterpret_cast<uint4*>(sW + n * WSTR) + q4;
#pragma unroll
            for (int i = 0; i < 4; i++) sw[i] = gw[i];
        }
        __syncthreads();

        float acc[32];
#pragma unroll
        for (int i = 0; i < 32; i++) acc[i] = 0.f;

#pragma unroll
        for (int ks = 0; ks < 8; ks++) {
            uint32_t kb = (uint32_t)(ks * 32);
            uint32_t ah0[4], ah1[4];
            ldsm4(ah0, aA0 + kb);
            ldsm4(ah1, aA0 + A_MB + kb);
#pragma unroll
            for (int np = 0; np < 2; np++) {
                uint32_t bh[4];
                ldsm4(bh, aB0 + np * B_NP + kb);
                float* d00 = acc + (0 * 4 + np * 2) * 4;
                float* d01 = acc + (0 * 4 + np * 2 + 1) * 4;
                float* d10 = acc + (1 * 4 + np * 2) * 4;
                float* d11 = acc + (1 * 4 + np * 2 + 1) * 4;
                mma_f16(d00, ah0, bh[0], bh[1]);
                mma_f16(d01, ah0, bh[2], bh[3]);
                mma_f16(d10, ah1, bh[0], bh[1]);
                mma_f16(d11, ah1, bh[2], bh[3]);
            }
        }

        // ---- Flush ----
        int rq = lane >> 2;
        int cq = 2 * (lane & 3);
#pragma unroll
        for (int mb = 0; mb < 2; mb++) {
#pragma unroll
            for (int nb = 0; nb < 4; nb++) {
                float* d = acc + (mb * 4 + nb) * 4;
                int r0 = base + rg * 32 + mb * 16 + rq;
                int col = h * 64 + cg * 32 + nb * 8 + cq;
                if (col < NSELF) {
                    if (r0 < M)
                        *reinterpret_cast<float2*>(&Cself[(size_t)r0 * NSELF + col]) =
                            make_float2(d[0], d[1]);
                    if (r0 + 8 < M)
                        *reinterpret_cast<float2*>(&Cself[(size_t)(r0 + 8) * NSELF + col]) =
                            make_float2(d[2], d[3]);
                } else {
                    int pc = col - NSELF;
                    if (r0 < M)
                        *reinterpret_cast<__half2*>(&Pneigh[(size_t)r0 * NP + pc]) =
                            __floats2half2_rn(d[0], d[1]);
                    if (r0 + 8 < M)
                        *reinterpret_cast<__half2*>(&Pneigh[(size_t)(r0 + 8) * NP + pc]) =
                            __floats2half2_rn(d[2], d[3]);
                }
            }
        }
    }
}

// ---------------------------------------------------------------------------
// Fused CSR aggregation + epilogue, layer 1 (frozen since round 13).
// ---------------------------------------------------------------------------
__global__ void agg_fin1_kernel(const float* __restrict__ b1) {
    int node = (blockIdx.x * blockDim.x + threadIdx.x) >> 5;
    int lane = threadIdx.x & 31;
    if (node >= NNODES) return;

    int beg = g_off[node];
    int cnt = g_cnt[node];
    int end = beg + cnt;

    const uint2* P = reinterpret_cast<const uint2*>(g_P1);
    float4 a0 = make_float4(0.f, 0.f, 0.f, 0.f);
    float4 a1 = a0, a2 = a0, a3 = a0;

    int j = beg;
    for (; j + 4 <= end; j += 4) {
        int s0 = g_csr[j];
        int s1 = g_csr[j + 1];
        int s2 = g_csr[j + 2];
        int s3 = g_csr[j + 3];
        a0 = f4addh(a0, P[(size_t)s0 * 32 + lane]);
        a1 = f4addh(a1, P[(size_t)s1 * 32 + lane]);
        a2 = f4addh(a2, P[(size_t)s2 * 32 + lane]);
        a3 = f4addh(a3, P[(size_t)s3 * 32 + lane]);
    }
    for (; j < end; j++) {
        int s = g_csr[j];
        a0 = f4addh(a0, P[(size_t)s * 32 + lane]);
    }
    float4 sum = f4add(f4add(a0, a1), f4add(a2, a3));

    float rdeg = 1.0f / fmaxf((float)cnt, 1.0f);
    float4 self = reinterpret_cast<const float4*>(g_C1s)[node * 32 + lane];
    float4 bb = reinterpret_cast<const float4*>(b1)[lane];
    float hx = fmaxf(fmaf(sum.x, rdeg, self.x) + bb.x, 0.f);
    float hy = fmaxf(fmaf(sum.y, rdeg, self.y) + bb.y, 0.f);
    float hz = fmaxf(fmaf(sum.z, rdeg, self.z) + bb.z, 0.f);
    float hw = fmaxf(fmaf(sum.w, rdeg, self.w) + bb.w, 0.f);
    __half2 p0 = __floats2half2_rn(hx, hy);
    __half2 p1 = __floats2half2_rn(hz, hw);
    uint2 st;
    st.x = *reinterpret_cast<uint32_t*>(&p0);
    st.y = *reinterpret_cast<uint32_t*>(&p1);
    *reinterpret_cast<uint2*>(&g_H1[(size_t)node * 128 + lane * 4]) = st;
}

// ---------------------------------------------------------------------------
// Fused CSR aggregation + epilogue, layer 2 (frozen since round 13).
// ---------------------------------------------------------------------------
__global__ void agg_fin2_kernel(const float* __restrict__ b2,
                                float4* __restrict__ out) {
    int grp = (blockIdx.x * blockDim.x + threadIdx.x) >> 4;
    int lane = threadIdx.x & 15;
    if (grp >= NNODES) return;
    int node = grp;

    int beg = g_off[node];
    int cnt = g_cnt[node];
    int end = beg + cnt;

    const uint2* P = reinterpret_cast<const uint2*>(g_P2);
    float4 a0 = make_float4(0.f, 0.f, 0.f, 0.f);
    float4 a1 = a0, a2 = a0, a3 = a0;

    int j = beg;
    for (; j + 4 <= end; j += 4) {
        int s0 = g_csr[j];
        int s1 = g_csr[j + 1];
        int s2 = g_csr[j + 2];
        int s3 = g_csr[j + 3];
        a0 = f4addh(a0, P[(size_t)s0 * 16 + lane]);
        a1 = f4addh(a1, P[(size_t)s1 * 16 + lane]);
        a2 = f4addh(a2, P[(size_t)s2 * 16 + lane]);
        a3 = f4addh(a3, P[(size_t)s3 * 16 + lane]);
    }
    for (; j < end; j++) {
        int s = g_csr[j];
        a0 = f4addh(a0, P[(size_t)s * 16 + lane]);
    }
    float4 sum = f4add(f4add(a0, a1), f4add(a2, a3));

    float rdeg = 1.0f / fmaxf((float)cnt, 1.0f);
    float4 self = reinterpret_cast<const float4*>(g_C2s)[node * 16 + lane];
    float4 bb = reinterpret_cast<const float4*>(b2)[lane];
    float4 o;
    o.x = fmaf(sum.x, rdeg, self.x) + bb.x;
    o.y = fmaf(sum.y, rdeg, self.y) + bb.y;
    o.z = fmaf(sum.z, rdeg, self.z) + bb.z;
    o.w = fmaf(sum.w, rdeg, self.w) + bb.w;
    out[node * 16 + lane] = o;
}

// ---------------------------------------------------------------------------
// Launch. CSR on side stream overlapped with prep + GEMM1 on main.
// ---------------------------------------------------------------------------
extern "C" void kernel_launch(void* const* d_in, const int* in_sizes, int n_in,
                              void* d_out, int out_size) {
    const float* x   = (const float*)d_in[0];
    const float* Ws1 = (const float*)d_in[1];
    const float* Wn1 = (const float*)d_in[2];
    const float* b1  = (const float*)d_in[3];
    const float* Ws2 = (const float*)d_in[4];
    const float* Wn2 = (const float*)d_in[5];
    const float* b2  = (const float*)d_in[6];
    const int*   src = (const int*)d_in[7];
    const int*   dst = (const int*)d_in[8];
    float4* out = (float4*)d_out;

    float *c1s = nullptr, *c2s = nullptr;
    __half *p1 = nullptr, *p2 = nullptr, *h1 = nullptr, *x16 = nullptr;
    __half *w1 = nullptr, *w2 = nullptr;
    cudaGetSymbolAddress((void**)&x16, g_X16);
    cudaGetSymbolAddress((void**)&c1s, g_C1s);
    cudaGetSymbolAddress((void**)&p1,  g_P1);
    cudaGetSymbolAddress((void**)&h1,  g_H1);
    cudaGetSymbolAddress((void**)&c2s, g_C2s);
    cudaGetSymbolAddress((void**)&p2,  g_P2);
    cudaGetSymbolAddress((void**)&w1,  g_W1);
    cudaGetSymbolAddress((void**)&w2,  g_W2);

    static cudaStream_t s_side = nullptr;
    static cudaEvent_t  s_fork = nullptr, s_join = nullptr;
    if (s_side == nullptr) {
        cudaStreamCreateWithFlags(&s_side, cudaStreamNonBlocking);
        cudaEventCreateWithFlags(&s_fork, cudaEventDisableTiming);
        cudaEventCreateWithFlags(&s_join, cudaEventDisableTiming);
    }

    const int SCAN_BLOCKS = (NNODES + 511) / 512;            // 98
    const int GTILES = (NNODES + 127) / 128;                 // 391
    // SMEM: A fp16 128*136*2 + W fp16 64*136*2 = 52224 bytes
    const int GSMEM = 128 * 136 * 2 + 64 * 136 * 2;

    cudaFuncSetAttribute((const void*)gemm_mma_kernel<256, 128>,
                         cudaFuncAttributeMaxDynamicSharedMemorySize, GSMEM);
    cudaFuncSetAttribute((const void*)gemm_mma_kernel<128, 64>,
                         cudaFuncAttributeMaxDynamicSharedMemorySize, GSMEM);

    // ---- Fork ----
    cudaEventRecord(s_fork, 0);
    cudaStreamWaitEvent(s_side, s_fork, 0);

    // Launches #1-#2: prep (main), zero (side)
    prep_kernel<<<512, 256>>>(x, Ws1, Wn1, Ws2, Wn2);
    zero_cnt_kernel<<<(NNODES + 255) / 256, 256, 0, s_side>>>();

    // Launch #3: GEMM1
    gemm_mma_kernel<256, 128><<<GTILES, 256, GSMEM>>>(
        x16, w1, c1s, p1, NNODES);

    // Launches #4-#7: rest of CSR chain (side stream)
    hist_kernel<<<(NEDGES + 255) / 256, 256, 0, s_side>>>(dst);
    scanA_kernel<<<SCAN_BLOCKS, 512, 0, s_side>>>();
    scanC_kernel<<<(NNODES + 255) / 256, 256, 0, s_side>>>(SCAN_BLOCKS);
    scatter_kernel<<<(NEDGES + 255) / 256, 256, 0, s_side>>>(src, dst);
    cudaEventRecord(s_join, s_side);

    // ---- Join: aggregation needs CSR ----
    cudaStreamWaitEvent(0, s_join, 0);
    agg_fin1_kernel<<<(NNODES * 32 + 255) / 256, 256>>>(b1);

    gemm_mma_kernel<128, 64><<<GTILES, 256, GSMEM>>>(
        h1, w2, c2s, p2, NNODES);
    agg_fin2_kernel<<<(NNODES * 16 + 255) / 256, 256>>>(b2, out);
}